// round 1
// baseline (speedup 1.0000x reference)
#include <cuda_runtime.h>
#include <stdint.h>

#define NB   256
#define NK   64
#define NL   32
#define SENT 32
#define TBL  4096
#define TMASK 4095u
#define EMPTYV 0xFFFFFFFFu
#define NODE_MASK 0x1FFFFu   // node ids < 100000 < 2^17

__device__ __forceinline__ int ht_lookup(const uint32_t* __restrict__ tab, uint32_t node) {
    uint32_t h = (node * 2654435761u) & TMASK;
    #pragma unroll 1
    for (;;) {
        uint32_t cur = tab[h];
        if (cur == EMPTYV) return SENT;                 // not in other walk set
        if ((cur & NODE_MASK) == node) return (int)(cur >> 17);
        h = (h + 1) & TMASK;
    }
}

__global__ __launch_bounds__(512, 4) void wpe_kernel(
    const int* __restrict__ src_walks, const int* __restrict__ tgt_walks,
    const int* __restrict__ src_lens,  const int* __restrict__ tgt_lens,
    const float* __restrict__ own_emb, const float* __restrict__ cross_emb,
    float* __restrict__ out)
{
    __shared__ uint32_t s_tab[2][TBL];   // [0]=src first-seen, [1]=tgt first-seen
    const int b    = blockIdx.x;
    const int side = blockIdx.y;         // 0: emit src_pos, 1: emit tgt_pos
    const int tid  = threadIdx.x;

    // init hash tables
    for (int i = tid; i < 2 * TBL; i += 512)
        (&s_tab[0][0])[i] = EMPTYV;
    __syncthreads();

    // build BOTH tables (cross-perspective lookups need the other side)
    #pragma unroll
    for (int s = 0; s < 2; s++) {
        const int* w  = (s == 0 ? src_walks : tgt_walks) + b * NK * NL;
        const int* ln = (s == 0 ? src_lens  : tgt_lens)  + b * NK;
        uint32_t* tab = s_tab[s];
        for (int m = tid; m < NK * NL; m += 512) {
            int node = w[m];
            int l = m & (NL - 1);
            if (node != 0 && l < ln[m >> 5]) {
                uint32_t packed = ((uint32_t)l << 17) | (uint32_t)node;
                uint32_t h = ((uint32_t)node * 2654435761u) & TMASK;
                #pragma unroll 1
                for (;;) {
                    uint32_t cur = tab[h];
                    if (cur == EMPTYV) {
                        cur = atomicCAS(&tab[h], EMPTYV, packed);
                        if (cur == EMPTYV) break;       // claimed empty slot
                    }
                    if ((cur & NODE_MASK) == (uint32_t)node) {
                        // same key: packed-min == pos-min (key bits identical)
                        atomicMin(&tab[h], packed);
                        break;
                    }
                    h = (h + 1) & TMASK;
                }
            }
        }
    }
    __syncthreads();

    // emit: one warp per (k,l) entry, 128 floats = 32 lanes x float4
    const int* w  = (side == 0 ? src_walks : tgt_walks) + b * NK * NL;
    const int* ln = (side == 0 ? src_lens  : tgt_lens)  + b * NK;
    const float4* oe = (const float4*)own_emb;    // 33 rows x 16 float4
    const float4* ce = (const float4*)cross_emb;
    const uint32_t* mytab = s_tab[side];
    const uint32_t* xtab  = s_tab[side ^ 1];
    float4* outp = (float4*)out + ((size_t)side * NB + b) * (size_t)(NK * NL * 32);

    const int warp = tid >> 5, lane = tid & 31;
    for (int m = warp; m < NK * NL; m += 16) {
        int node = w[m];                 // warp-uniform broadcast load
        int l = m & (NL - 1);
        float4 v = make_float4(0.f, 0.f, 0.f, 0.f);
        if (node != 0 && l < ln[m >> 5]) {
            int own   = ht_lookup(mytab, (uint32_t)node);  // always present
            int cross = ht_lookup(xtab,  (uint32_t)node);  // may be SENT
            v = (lane < 16) ? __ldg(&oe[own * 16 + lane])
                            : __ldg(&ce[cross * 16 + (lane & 15)]);
        }
        outp[(size_t)m * 32 + lane] = v;  // 512B fully coalesced per warp
    }
}

extern "C" void kernel_launch(void* const* d_in, const int* in_sizes, int n_in,
                              void* d_out, int out_size) {
    (void)in_sizes; (void)n_in; (void)out_size;
    dim3 grid(NB, 2);
    wpe_kernel<<<grid, 512>>>(
        (const int*)d_in[0], (const int*)d_in[1],
        (const int*)d_in[2], (const int*)d_in[3],
        (const float*)d_in[4], (const float*)d_in[5],
        (float*)d_out);
}

// round 2
// speedup vs baseline: 1.0585x; 1.0585x over previous
#include <cuda_runtime.h>
#include <stdint.h>

#define NB   256
#define NK   64
#define NL   32
#define NM   (NK * NL)        // 2048 entries per (batch, side)
#define SENT 32
#define TBL  4096
#define TMASK 4095u
#define EMPTYV 0xFFFFFFFFu
#define NODE_MASK 0x1FFFFu    // node ids < 100000 < 2^17

__device__ __forceinline__ int ht_lookup(const uint32_t* __restrict__ tab, uint32_t node) {
    uint32_t h = (node * 2654435761u) & TMASK;
    #pragma unroll 1
    for (;;) {
        uint32_t cur = tab[h];
        if (cur == EMPTYV) return SENT;                 // absent -> sentinel
        if ((cur & NODE_MASK) == node) return (int)(cur >> 17);
        h = (h + 1) & TMASK;
    }
}

__global__ __launch_bounds__(512, 4) void wpe_kernel(
    const int* __restrict__ src_walks, const int* __restrict__ tgt_walks,
    const int* __restrict__ src_lens,  const int* __restrict__ tgt_lens,
    const float* __restrict__ own_emb, const float* __restrict__ cross_emb,
    float* __restrict__ out)
{
    __shared__ uint32_t s_tab[2][TBL];    // 32 KB: [0]=src table, [1]=tgt table
    __shared__ uint16_t s_pos[NM];        // 4 KB: packed own|cross<<6|valid<<15
    const int b    = blockIdx.x;
    const int side = blockIdx.y;          // 0: emit src_pos, 1: emit tgt_pos
    const int tid  = threadIdx.x;

    for (int i = tid; i < 2 * TBL; i += 512)
        (&s_tab[0][0])[i] = EMPTYV;
    __syncthreads();

    // ── build both first-seen tables (needed for cross-perspective) ──
    #pragma unroll
    for (int s = 0; s < 2; s++) {
        const int* w  = (s == 0 ? src_walks : tgt_walks) + b * NM;
        const int* ln = (s == 0 ? src_lens  : tgt_lens)  + b * NK;
        uint32_t* tab = s_tab[s];
        for (int m = tid; m < NM; m += 512) {
            int node = w[m];
            int l = m & (NL - 1);
            if (node != 0 && l < ln[m >> 5]) {
                uint32_t packed = ((uint32_t)l << 17) | (uint32_t)node;
                uint32_t h = ((uint32_t)node * 2654435761u) & TMASK;
                #pragma unroll 1
                for (;;) {
                    uint32_t cur = tab[h];
                    if (cur == EMPTYV) {
                        cur = atomicCAS(&tab[h], EMPTYV, packed);
                        if (cur == EMPTYV) break;
                    }
                    if ((cur & NODE_MASK) == (uint32_t)node) {
                        atomicMin(&tab[h], packed);   // same key: packed-min == pos-min
                        break;
                    }
                    h = (h + 1) & TMASK;
                }
            }
        }
    }
    __syncthreads();

    // ── phase A: resolve all 2048 (own, cross, valid) once; 4 per thread ──
    {
        const int* w  = (side == 0 ? src_walks : tgt_walks) + b * NM;
        const int* ln = (side == 0 ? src_lens  : tgt_lens)  + b * NK;
        const uint32_t* mytab = s_tab[side];
        const uint32_t* xtab  = s_tab[side ^ 1];
        #pragma unroll
        for (int r = 0; r < NM / 512; r++) {
            int m = tid + r * 512;
            int node = w[m];
            int l = m & (NL - 1);
            uint16_t p = 0;
            if (node != 0 && l < ln[m >> 5]) {
                int own   = ht_lookup(mytab, (uint32_t)node);
                int cross = ht_lookup(xtab,  (uint32_t)node);
                p = (uint16_t)(own | (cross << 6) | 0x8000);
            }
            s_pos[m] = p;
        }
    }
    __syncthreads();

    // ── phase B: emit. one warp per entry: 32 lanes x float4 = 512 B ──
    const float4* oe = (const float4*)own_emb;     // 33 rows x 16 float4
    const float4* ce = (const float4*)cross_emb;
    float4* outp = (float4*)out + ((size_t)side * NB + b) * (size_t)(NM * 32);

    const int warp = tid >> 5, lane = tid & 31;
    const int half = lane >> 4, col = lane & 15;
    #pragma unroll 4
    for (int m = warp; m < NM; m += 16) {
        uint32_t p = s_pos[m];                      // broadcast LDS
        float4 v = make_float4(0.f, 0.f, 0.f, 0.f);
        if (p & 0x8000u) {
            int own   = p & 63;
            int cross = (p >> 6) & 63;
            v = half ? __ldg(&ce[cross * 16 + col])
                     : __ldg(&oe[own   * 16 + col]);
        }
        __stcs(&outp[(size_t)m * 32 + lane], v);    // streaming: no L2 allocate
    }
}

extern "C" void kernel_launch(void* const* d_in, const int* in_sizes, int n_in,
                              void* d_out, int out_size) {
    (void)in_sizes; (void)n_in; (void)out_size;
    dim3 grid(NB, 2);
    wpe_kernel<<<grid, 512>>>(
        (const int*)d_in[0], (const int*)d_in[1],
        (const int*)d_in[2], (const int*)d_in[3],
        (const float*)d_in[4], (const float*)d_in[5],
        (float*)d_out);
}

// round 3
// speedup vs baseline: 1.0736x; 1.0142x over previous
#include <cuda_runtime.h>
#include <stdint.h>

#define NB   256
#define NK   64
#define NL   32
#define NM   (NK * NL)            // 2048 entries per (batch, side)
#define NTOT (2 * NB * NM)        // 1,048,576 total output rows
#define SENT 32
#define TBL  4096
#define TMASK 4095u
#define EMPTYV 0xFFFFFFFFu
#define NODE_MASK 0x1FFFFu        // node ids < 100000 < 2^17

#define EMIT_CTAS 592             // 4 * 148: exactly 4 resident CTAs per SM
#define EMIT_THREADS 512
#define EMIT_WARPS (EMIT_CTAS * (EMIT_THREADS / 32))   // 9472

// resolved position codes: own | cross<<6 | valid<<15, indexed [side][b][m]
__device__ uint16_t g_pos[NTOT];

__device__ __forceinline__ int ht_lookup(const uint32_t* __restrict__ tab, uint32_t node) {
    uint32_t h = (node * 2654435761u) & TMASK;
    #pragma unroll 1
    for (;;) {
        uint32_t cur = tab[h];
        if (cur == EMPTYV) return SENT;
        if ((cur & NODE_MASK) == node) return (int)(cur >> 17);
        h = (h + 1) & TMASK;
    }
}

// ── kernel 1: one CTA per batch; build both tables, resolve all 4096 codes ──
__global__ __launch_bounds__(512) void build_resolve_kernel(
    const int* __restrict__ src_walks, const int* __restrict__ tgt_walks,
    const int* __restrict__ src_lens,  const int* __restrict__ tgt_lens)
{
    __shared__ uint32_t s_tab[2][TBL];
    const int b   = blockIdx.x;
    const int tid = threadIdx.x;

    for (int i = tid; i < 2 * TBL; i += 512)
        (&s_tab[0][0])[i] = EMPTYV;
    __syncthreads();

    #pragma unroll
    for (int s = 0; s < 2; s++) {
        const int* w  = (s == 0 ? src_walks : tgt_walks) + b * NM;
        const int* ln = (s == 0 ? src_lens  : tgt_lens)  + b * NK;
        uint32_t* tab = s_tab[s];
        for (int m = tid; m < NM; m += 512) {
            int node = w[m];
            int l = m & (NL - 1);
            if (node != 0 && l < ln[m >> 5]) {
                uint32_t packed = ((uint32_t)l << 17) | (uint32_t)node;
                uint32_t h = ((uint32_t)node * 2654435761u) & TMASK;
                #pragma unroll 1
                for (;;) {
                    uint32_t cur = tab[h];
                    if (cur == EMPTYV) {
                        cur = atomicCAS(&tab[h], EMPTYV, packed);
                        if (cur == EMPTYV) break;
                    }
                    if ((cur & NODE_MASK) == (uint32_t)node) {
                        atomicMin(&tab[h], packed);  // same key: packed-min == pos-min
                        break;
                    }
                    h = (h + 1) & TMASK;
                }
            }
        }
    }
    __syncthreads();

    #pragma unroll
    for (int side = 0; side < 2; side++) {
        const int* w  = (side == 0 ? src_walks : tgt_walks) + b * NM;
        const int* ln = (side == 0 ? src_lens  : tgt_lens)  + b * NK;
        const uint32_t* mytab = s_tab[side];
        const uint32_t* xtab  = s_tab[side ^ 1];
        uint16_t* gp = g_pos + ((size_t)side * NB + b) * NM;
        #pragma unroll
        for (int r = 0; r < NM / 512; r++) {
            int m = tid + r * 512;
            int node = w[m];
            int l = m & (NL - 1);
            uint16_t p = 0;
            if (node != 0 && l < ln[m >> 5]) {
                int own   = ht_lookup(mytab, (uint32_t)node);
                int cross = ht_lookup(xtab,  (uint32_t)node);
                p = (uint16_t)(own | (cross << 6) | 0x8000);
            }
            gp[m] = p;
        }
    }
}

// ── kernel 2: persistent balanced streaming emit ──
__global__ __launch_bounds__(EMIT_THREADS, 4) void emit_kernel(
    const float* __restrict__ own_emb, const float* __restrict__ cross_emb,
    float* __restrict__ out)
{
    const float4* oe = (const float4*)own_emb;     // 33 rows x 16 float4
    const float4* ce = (const float4*)cross_emb;
    float4* out4 = (float4*)out;

    const int lane = threadIdx.x & 31;
    const int gw   = blockIdx.x * (EMIT_THREADS / 32) + (threadIdx.x >> 5);
    const int half = lane >> 4, col = lane & 15;

    // each warp: groups of 4 consecutive entries, grid-strided
    for (int e0 = gw * 4; e0 < NTOT; e0 += EMIT_WARPS * 4) {
        uint32_t p[4];
        #pragma unroll
        for (int j = 0; j < 4; j++) p[j] = g_pos[e0 + j];   // broadcast, L2-hit

        float4 v[4];
        #pragma unroll
        for (int j = 0; j < 4; j++) {
            v[j] = make_float4(0.f, 0.f, 0.f, 0.f);
            if (p[j] & 0x8000u) {
                int own   = p[j] & 63;
                int cross = (p[j] >> 6) & 63;
                v[j] = half ? __ldg(&ce[cross * 16 + col])
                            : __ldg(&oe[own   * 16 + col]);
            }
        }
        #pragma unroll
        for (int j = 0; j < 4; j++)
            __stcs(&out4[(size_t)(e0 + j) * 32 + lane], v[j]);
    }
}

extern "C" void kernel_launch(void* const* d_in, const int* in_sizes, int n_in,
                              void* d_out, int out_size) {
    (void)in_sizes; (void)n_in; (void)out_size;
    build_resolve_kernel<<<NB, 512>>>(
        (const int*)d_in[0], (const int*)d_in[1],
        (const int*)d_in[2], (const int*)d_in[3]);
    emit_kernel<<<EMIT_CTAS, EMIT_THREADS>>>(
        (const float*)d_in[4], (const float*)d_in[5],
        (float*)d_out);
}

// round 4
// speedup vs baseline: 1.1019x; 1.0263x over previous
#include <cuda_runtime.h>
#include <stdint.h>

#define NB   256
#define NK   64
#define NL   32
#define NM   (NK * NL)            // 2048 entries (rows) per (side, batch) block
#define NTOT (2 * NB * NM)        // 1,048,576 output rows total
#define SENT 32
#define TBL  4096
#define TMASK 4095u
#define EMPTYV 0xFFFFFFFFu
#define NODE_MASK 0x1FFFFu        // node ids < 100000 < 2^17

#define CTAS 592                  // 4 * 148 SMs: one full resident wave
#define RPC  1772                 // ceil(NTOT / CTAS); slice spans <= 2 blocks

__device__ __forceinline__ int ht_lookup(const uint32_t* __restrict__ tab, uint32_t node) {
    uint32_t h = (node * 2654435761u) & TMASK;
    #pragma unroll 1
    for (;;) {
        uint32_t cur = tab[h];
        if (cur == EMPTYV) return SENT;
        if ((cur & NODE_MASK) == node) return (int)(cur >> 17);
        h = (h + 1) & TMASK;
    }
}

__global__ __launch_bounds__(512, 4) void wpe_fused_kernel(
    const int* __restrict__ src_walks, const int* __restrict__ tgt_walks,
    const int* __restrict__ src_lens,  const int* __restrict__ tgt_lens,
    const float* __restrict__ own_emb, const float* __restrict__ cross_emb,
    float* __restrict__ out)
{
    __shared__ uint32_t s_tab[2][TBL];    // 32 KB: first-seen tables for current batch
    __shared__ uint16_t s_code[NM];       // 4 KB: resolved codes for current segment

    const int tid  = threadIdx.x;
    const int warp = tid >> 5, lane = tid & 31;
    const int half = lane >> 4, col = lane & 15;

    const float4* oe = (const float4*)own_emb;     // 33 rows x 16 float4
    const float4* ce = (const float4*)cross_emb;
    float4* out4 = (float4*)out;

    long r0 = (long)blockIdx.x * RPC;
    long r1 = r0 + RPC; if (r1 > NTOT) r1 = NTOT;

    for (long s = r0; s < r1; ) {
        long blk_end = ((s >> 11) + 1) << 11;         // end of current 2048-row block
        long e = (r1 < blk_end) ? r1 : blk_end;
        const int side = (int)(s >> 19);              // 0: src rows, 1: tgt rows
        const int b    = (int)((s >> 11) & (NB - 1));

        // ── build both first-seen hash tables for batch b ──
        __syncthreads();                              // previous segment done with smem
        for (int i = tid; i < 2 * TBL; i += 512)
            (&s_tab[0][0])[i] = EMPTYV;
        __syncthreads();

        #pragma unroll
        for (int t = 0; t < 2; t++) {
            const int* w  = (t == 0 ? src_walks : tgt_walks) + b * NM;
            const int* ln = (t == 0 ? src_lens  : tgt_lens)  + b * NK;
            uint32_t* tab = s_tab[t];
            #pragma unroll
            for (int rr = 0; rr < NM / 512; rr++) {
                int m = tid + rr * 512;
                int node = w[m];
                int l = m & (NL - 1);
                if (node != 0 && l < ln[m >> 5]) {
                    uint32_t packed = ((uint32_t)l << 17) | (uint32_t)node;
                    uint32_t h = ((uint32_t)node * 2654435761u) & TMASK;
                    #pragma unroll 1
                    for (;;) {
                        uint32_t cur = tab[h];
                        if (cur == EMPTYV) {
                            cur = atomicCAS(&tab[h], EMPTYV, packed);
                            if (cur == EMPTYV) break;
                        }
                        if ((cur & NODE_MASK) == (uint32_t)node) {
                            atomicMin(&tab[h], packed);   // same key: packed-min == pos-min
                            break;
                        }
                        h = (h + 1) & TMASK;
                    }
                }
            }
        }
        __syncthreads();

        // ── resolve codes for rows [s, e): each thread independent lookups ──
        const int* w  = (side == 0 ? src_walks : tgt_walks) + b * NM;
        const int* ln = (side == 0 ? src_lens  : tgt_lens)  + b * NK;
        const uint32_t* mytab = s_tab[side];
        const uint32_t* xtab  = s_tab[side ^ 1];
        const int cnt   = (int)(e - s);
        const int mbase = (int)(s & (NM - 1));

        for (int i = tid; i < cnt; i += 512) {
            int m = mbase + i;
            int node = w[m];
            int l = m & (NL - 1);
            uint16_t p = 0;
            if (node != 0 && l < ln[m >> 5]) {
                int own   = ht_lookup(mytab, (uint32_t)node);
                int cross = ht_lookup(xtab,  (uint32_t)node);
                p = (uint16_t)(own | (cross << 6) | 0x8000);
            }
            s_code[i] = p;
        }
        __syncthreads();

        // ── emit rows [s, e): one warp per row, 32 lanes x float4 = 512 B ──
        int i = warp;
        for (; i + 64 <= cnt; i += 64) {              // 4-deep batches for store MLP
            uint32_t p[4]; float4 v[4];
            #pragma unroll
            for (int j = 0; j < 4; j++) p[j] = s_code[i + j * 16];
            #pragma unroll
            for (int j = 0; j < 4; j++) {
                v[j] = make_float4(0.f, 0.f, 0.f, 0.f);
                if (p[j] & 0x8000u) {
                    int own   = p[j] & 63;
                    int cross = (p[j] >> 6) & 63;
                    v[j] = half ? __ldg(&ce[cross * 16 + col])
                                : __ldg(&oe[own   * 16 + col]);
                }
            }
            #pragma unroll
            for (int j = 0; j < 4; j++)
                __stcs(&out4[(size_t)(s + i + j * 16) * 32 + lane], v[j]);
        }
        for (; i < cnt; i += 16) {                    // remainder
            uint32_t p = s_code[i];
            float4 v = make_float4(0.f, 0.f, 0.f, 0.f);
            if (p & 0x8000u) {
                int own   = p & 63;
                int cross = (p >> 6) & 63;
                v = half ? __ldg(&ce[cross * 16 + col])
                         : __ldg(&oe[own   * 16 + col]);
            }
            __stcs(&out4[(size_t)(s + i) * 32 + lane], v);
        }

        s = e;
    }
}

extern "C" void kernel_launch(void* const* d_in, const int* in_sizes, int n_in,
                              void* d_out, int out_size) {
    (void)in_sizes; (void)n_in; (void)out_size;
    wpe_fused_kernel<<<CTAS, 512>>>(
        (const int*)d_in[0], (const int*)d_in[1],
        (const int*)d_in[2], (const int*)d_in[3],
        (const float*)d_in[4], (const float*)d_in[5],
        (float*)d_out);
}